// round 1
// baseline (speedup 1.0000x reference)
#include <cuda_runtime.h>
#include <cstdint>

#define E 128
#define L 64
#define NEG_INF -100000000.0f
#define MAX_B 8192
#define ROWS_PER_BLK 32
#define MAX_PARTS (MAX_B / ROWS_PER_BLK)

// Scratch (no allocations allowed)
__device__ __align__(16) float g_feats[3ull * MAX_B * E];
__device__ float g_part[3 * MAX_PARTS];
__device__ float g_scores[3];

// Dynamic smem layout (floats):
// [0..128)    s_self
// [128..256)  s_wlo
// [256..384)  s_whi
// [384..448)  s_log (64)
// [448..456)  s_red (8)
// [456..520)  idxA (as int, 64)
// [520..584)  idxB (as int, 64)
// [640..640+8192)           tileA (64*128)
// [640+8192..640+16384)     tileB (64*128)  -- only when HASB
#define SMEM_HDR 640
#define SMEM_BYTES_FALSE ((SMEM_HDR + L * E) * 4)
#define SMEM_BYTES_TRUE  ((SMEM_HDR + 2 * L * E) * 4)

template <bool HASB>
__global__ __launch_bounds__(128) void branch_kernel(
    const float* __restrict__ tabA, const float* __restrict__ tabB,
    const float* __restrict__ user_embs, const float* __restrict__ w,
    const int* __restrict__ uid, const int* __restrict__ idx, int idx_stride,
    float scale, int br, int B)
{
    extern __shared__ float smem[];
    float* s_self = smem;
    float* s_wlo  = smem + 128;
    float* s_whi  = smem + 256;
    float* s_log  = smem + 384;
    float* s_red  = smem + 448;
    int*   s_idxA = (int*)(smem + 456);
    int*   s_idxB = (int*)(smem + 520);
    float* tileA  = smem + SMEM_HDR;
    float* tileB  = smem + SMEM_HDR + L * E;

    const int t    = threadIdx.x;
    const int wid  = t >> 5;
    const int lane = t & 31;
    const int b    = blockIdx.x;

    const int* iA = idx + (size_t)b * idx_stride;

    const int u = uid[b];
    s_self[t] = user_embs[(size_t)u * E + t];
    s_wlo[t]  = w[t];
    s_whi[t]  = w[E + t];
    if (t < L) s_idxA[t] = iA[t];
    if (HASB && t >= L && t < 2 * L) s_idxB[t - L] = iA[t];  // iA[L + (t-L)]
    __syncthreads();

    // Gather: each warp loads rows l = wid, wid+4, ... via float4
#pragma unroll
    for (int l = wid; l < L; l += 4) {
        ((float4*)(tileA + l * E))[lane] =
            ((const float4*)(tabA + (size_t)s_idxA[l] * E))[lane];
    }
    if (HASB) {
#pragma unroll
        for (int l = wid; l < L; l += 4) {
            ((float4*)(tileB + l * E))[lane] =
                ((const float4*)(tabB + (size_t)s_idxB[l] * E))[lane];
        }
    }

    // Self dots (overlap with gather latency)
    float p0 = s_self[t] * s_wlo[t];
    float p1 = s_self[t] * s_whi[t];
#pragma unroll
    for (int o = 16; o > 0; o >>= 1) {
        p0 += __shfl_xor_sync(0xffffffffu, p0, o);
        p1 += __shfl_xor_sync(0xffffffffu, p1, o);
    }
    if (lane == 0) { s_red[wid] = p0; s_red[4 + wid] = p1; }
    __syncthreads();

    const float c_lo = s_red[0] + s_red[1] + s_red[2] + s_red[3];
    const float c_hi = s_red[4] + s_red[5] + s_red[6] + s_red[7];

    // Per-neighbor logits: warp 'wid' handles rows wid, wid+4, ...
    const float4 wh = ((const float4*)s_whi)[lane];
#pragma unroll
    for (int l = wid; l < L; l += 4) {
        float4 va = ((const float4*)(tileA + l * E))[lane];
        float d = va.x * wh.x + va.y * wh.y + va.z * wh.z + va.w * wh.w;
        if (HASB) {
            float4 vb = ((const float4*)(tileB + l * E))[lane];
            d += vb.x * wh.x + vb.y * wh.y + vb.z * wh.z + vb.w * wh.w;
        }
#pragma unroll
        for (int o = 16; o > 0; o >>= 1) d += __shfl_xor_sync(0xffffffffu, d, o);
        if (lane == 0) {
            float x = c_lo + scale * (c_hi + d);
            x = (x > 0.f) ? x : 0.01f * x;           // leaky_relu
            if (s_idxA[l] == 0) x += NEG_INF;        // mask
            s_log[l] = x;
        }
    }
    __syncthreads();

    // Softmax over L=64 in warp 0
    if (t < 32) {
        float v0 = s_log[t], v1 = s_log[t + 32];
        float m = fmaxf(v0, v1);
#pragma unroll
        for (int o = 16; o > 0; o >>= 1) m = fmaxf(m, __shfl_xor_sync(0xffffffffu, m, o));
        float e0 = expf(v0 - m), e1 = expf(v1 - m);
        float s = e0 + e1;
#pragma unroll
        for (int o = 16; o > 0; o >>= 1) s += __shfl_xor_sync(0xffffffffu, s, o);
        float inv = 1.f / s;
        s_log[t] = e0 * inv;
        s_log[t + 32] = e1 * inv;
    }
    __syncthreads();

    // Weighted sum over neighbors: thread t owns element t
    float accA = 0.f, accB = 0.f;
#pragma unroll
    for (int l = 0; l < L; l++) {
        float a = s_log[l];
        accA += a * tileA[l * E + t];
        if (HASB) accB += a * tileB[l * E + t];
    }
    float f = scale * (s_self[t] + accA + accB);
    g_feats[((size_t)br * B + b) * E + t] = fmaxf(f, 0.f);
}

// Scores: per-block partial of sum_b tanh(feat_b @ W0 + b0) . w1
__global__ __launch_bounds__(128) void scores_kernel(
    const float* __restrict__ W0, const float* __restrict__ b0,
    const float* __restrict__ w1, int B, int nparts)
{
    __shared__ float sW0[E * 64];
    __shared__ float sb0[64];
    __shared__ float sw1[64];
    __shared__ float sfeat[4][E];

    const int t = threadIdx.x;
    const int wid = t >> 5, lane = t & 31;
    for (int i = t; i < E * 64; i += 128) sW0[i] = W0[i];
    if (t < 64) { sb0[t] = b0[t]; sw1[t] = w1[t]; }
    __syncthreads();

    const int br = blockIdx.y;
    const int base = blockIdx.x * ROWS_PER_BLK;

    float local = 0.f;
    for (int r0 = 0; r0 < ROWS_PER_BLK; r0 += 4) {
        const int b = base + r0 + wid;
        float4 f4 = ((const float4*)(g_feats + ((size_t)br * B + b) * E))[lane];
        ((float4*)&sfeat[wid][0])[lane] = f4;
        __syncwarp();
        float acc0 = sb0[lane], acc1 = sb0[lane + 32];
#pragma unroll
        for (int e = 0; e < E; e++) {
            float v = sfeat[wid][e];
            acc0 += v * sW0[e * 64 + lane];
            acc1 += v * sW0[e * 64 + lane + 32];
        }
        float s = tanhf(acc0) * sw1[lane] + tanhf(acc1) * sw1[lane + 32];
#pragma unroll
        for (int o = 16; o > 0; o >>= 1) s += __shfl_xor_sync(0xffffffffu, s, o);
        if (lane == 0) local += s;
        __syncwarp();
    }
#pragma unroll
    for (int o = 2; o > 0; o >>= 1) local += __shfl_xor_sync(0xffffffffu, local, o); // no-op for lane!=0
    if (lane == 0) {
        // one value per warp? no: each warp produced its own rows; combine via smem
        sfeat[0][wid] = local;
    }
    __syncthreads();
    if (t == 0) {
        g_part[br * MAX_PARTS + blockIdx.x] =
            sfeat[0][0] + sfeat[0][1] + sfeat[0][2] + sfeat[0][3];
    }
}

__global__ void reduce_scores_kernel(int nparts) {
    const int br = blockIdx.x;
    const int t = threadIdx.x;
    float v = (t < nparts) ? g_part[br * MAX_PARTS + t] : 0.f;
#pragma unroll
    for (int o = 16; o > 0; o >>= 1) v += __shfl_xor_sync(0xffffffffu, v, o);
    __shared__ float red[4];
    if ((t & 31) == 0) red[t >> 5] = v;
    __syncthreads();
    if (t == 0) g_scores[br] = red[0] + red[1] + red[2] + red[3];
}

__global__ void mix_kernel(float* __restrict__ out, int B) {
    const int i = blockIdx.x * blockDim.x + threadIdx.x;
    const int total = B * E;
    if (i >= total) return;
    const float inv = 1.f / (float)B;
    float s0 = g_scores[0] * inv, s1 = g_scores[1] * inv, s2 = g_scores[2] * inv;
    float m = fmaxf(s0, fmaxf(s1, s2));
    float e0 = expf(s0 - m), e1 = expf(s1 - m), e2 = expf(s2 - m);
    float d = 1.f / (e0 + e1 + e2);
    float v = (e0 * g_feats[i] +
               e1 * g_feats[(size_t)B * E + i] +
               e2 * g_feats[(size_t)2 * B * E + i]) * d;
    out[i] = fmaxf(v, 0.f);
}

extern "C" void kernel_launch(void* const* d_in, const int* in_sizes, int n_in,
                              void* d_out, int out_size) {
    const float* user_embs = (const float*)d_in[0];
    const float* item_embs = (const float*)d_in[1];
    const float* w_uu  = (const float*)d_in[2];
    const float* w_uiu = (const float*)d_in[3];
    const float* w_uui = (const float*)d_in[4];
    const float* W0 = (const float*)d_in[5];
    const float* b0 = (const float*)d_in[6];
    const float* w1 = (const float*)d_in[7];
    const int* uid = (const int*)d_in[8];
    const int* nbr = (const int*)d_in[9];
    const int* uiu = (const int*)d_in[10];
    const int* uui = (const int*)d_in[11];
    float* out = (float*)d_out;

    const int B = in_sizes[8];

    static bool inited = false;
    if (!inited) {
        cudaFuncSetAttribute(branch_kernel<true>,
                             cudaFuncAttributeMaxDynamicSharedMemorySize, SMEM_BYTES_TRUE);
        cudaFuncSetAttribute(branch_kernel<false>,
                             cudaFuncAttributeMaxDynamicSharedMemorySize, SMEM_BYTES_FALSE);
        inited = true;
    }

    // Branch 0: uu  (feat = (self + user[nbr]) * 0.5, mask nbr==0)
    branch_kernel<false><<<B, 128, SMEM_BYTES_FALSE>>>(
        user_embs, nullptr, user_embs, w_uu, uid, nbr, L, 0.5f, 0, B);
    // Branch 1: uiu (feat = (self + item[uiu[:,0]] + user[uiu[:,1]])/3, mask uiu[:,0]==0)
    branch_kernel<true><<<B, 128, SMEM_BYTES_TRUE>>>(
        item_embs, user_embs, user_embs, w_uiu, uid, uiu, 2 * L, 1.f / 3.f, 1, B);
    // Branch 2: uui (feat = (self + user[uui[:,0]] + item[uui[:,1]])/3, mask uui[:,0]==0)
    branch_kernel<true><<<B, 128, SMEM_BYTES_TRUE>>>(
        user_embs, item_embs, user_embs, w_uui, uid, uui, 2 * L, 1.f / 3.f, 2, B);

    const int nparts = B / ROWS_PER_BLK;
    dim3 g2(nparts, 3);
    scores_kernel<<<g2, 128>>>(W0, b0, w1, B, nparts);
    reduce_scores_kernel<<<3, 128>>>(nparts);

    const int total = B * E;
    mix_kernel<<<(total + 255) / 256, 256>>>(out, B);
}

// round 2
// speedup vs baseline: 1.9107x; 1.9107x over previous
#include <cuda_runtime.h>
#include <cstdint>

#define E 128
#define L 64
#define NEG_INF -100000000.0f
#define MAX_B 8192
#define SROWS 16
#define MAX_PARTS (MAX_B / SROWS)

__device__ __align__(16) float g_feats[3ull * MAX_B * E];
__device__ float g_part[3 * MAX_PARTS];
__device__ float g_scores[3];

// ---------------------------------------------------------------------------
// Fused branch kernel: grid (B, 3), 256 threads. Register-resident gather rows.
// ---------------------------------------------------------------------------
__global__ __launch_bounds__(256) void branch_kernel(
    const float* __restrict__ user_embs, const float* __restrict__ item_embs,
    const float* __restrict__ w_uu, const float* __restrict__ w_uiu,
    const float* __restrict__ w_uui,
    const int* __restrict__ uid, const int* __restrict__ nbr,
    const int* __restrict__ uiu, const int* __restrict__ uui, int B)
{
    __shared__ int   s_idx[2 * L];     // A idx [0..64), B idx [64..128)
    __shared__ float s_self[E];
    __shared__ float s_whi[E];
    __shared__ float s_log[L];
    __shared__ float s_red[8];
    __shared__ float s_acc[8][E];

    const int t    = threadIdx.x;
    const int wid  = t >> 5;
    const int lane = t & 31;
    const int b    = blockIdx.x;
    const int br   = blockIdx.y;

    const float* tabA; const float* tabB; const float* w;
    const int* idx; int stride; float scale; bool hasB;
    if (br == 0)      { tabA = user_embs; tabB = user_embs; w = w_uu;  idx = nbr; stride = L;     scale = 0.5f;     hasB = false; }
    else if (br == 1) { tabA = item_embs; tabB = user_embs; w = w_uiu; idx = uiu; stride = 2 * L; scale = 1.f/3.f; hasB = true; }
    else              { tabA = user_embs; tabB = item_embs; w = w_uui; idx = uui; stride = 2 * L; scale = 1.f/3.f; hasB = true; }

    // Phase 0: cooperative loads. Warps 0-3: indices. Warps 4-7: self/w + dots.
    if (t < stride) s_idx[t] = idx[(size_t)b * stride + t];
    if (t >= 128) {
        const int e = t - 128;
        const int u = uid[b];
        const float se  = user_embs[(size_t)u * E + e];
        const float wlo = w[e];
        const float whi = w[E + e];
        s_self[e] = se;
        s_whi[e]  = whi;
        float p0 = se * wlo, p1 = se * whi;
#pragma unroll
        for (int o = 16; o > 0; o >>= 1) {
            p0 += __shfl_xor_sync(0xffffffffu, p0, o);
            p1 += __shfl_xor_sync(0xffffffffu, p1, o);
        }
        if (lane == 0) { s_red[wid - 4] = p0; s_red[4 + (wid - 4)] = p1; }
    }
    __syncthreads();

    // Phase 1: gather — each warp owns 8 neighbor rows, float4 per lane.
    float4 rowA[8], rowB[8];
#pragma unroll
    for (int r = 0; r < 8; r++) {
        const int l = wid * 8 + r;
        rowA[r] = ((const float4*)(tabA + (size_t)s_idx[l] * E))[lane];
    }
    if (hasB) {
#pragma unroll
        for (int r = 0; r < 8; r++) {
            const int l = wid * 8 + r;
            rowB[r] = ((const float4*)(tabB + (size_t)s_idx[L + l] * E))[lane];
        }
    }

    const float c_lo = s_red[0] + s_red[1] + s_red[2] + s_red[3];
    const float c_hi = s_red[4] + s_red[5] + s_red[6] + s_red[7];
    const float4 wh = ((const float4*)s_whi)[lane];

    // Phase 2: logits (one per owned row)
#pragma unroll
    for (int r = 0; r < 8; r++) {
        float d = rowA[r].x * wh.x + rowA[r].y * wh.y +
                  rowA[r].z * wh.z + rowA[r].w * wh.w;
        if (hasB)
            d += rowB[r].x * wh.x + rowB[r].y * wh.y +
                 rowB[r].z * wh.z + rowB[r].w * wh.w;
#pragma unroll
        for (int o = 16; o > 0; o >>= 1) d += __shfl_xor_sync(0xffffffffu, d, o);
        if (lane == 0) {
            const int l = wid * 8 + r;
            float x = c_lo + scale * (c_hi + d);
            x = (x > 0.f) ? x : 0.01f * x;
            if (s_idx[l] == 0) x += NEG_INF;
            s_log[l] = x;
        }
    }
    __syncthreads();

    // Phase 3: softmax over L=64 (warp 0)
    if (t < 32) {
        float v0 = s_log[t], v1 = s_log[t + 32];
        float m = fmaxf(v0, v1);
#pragma unroll
        for (int o = 16; o > 0; o >>= 1) m = fmaxf(m, __shfl_xor_sync(0xffffffffu, m, o));
        float e0 = expf(v0 - m), e1 = expf(v1 - m);
        float s = e0 + e1;
#pragma unroll
        for (int o = 16; o > 0; o >>= 1) s += __shfl_xor_sync(0xffffffffu, s, o);
        float inv = 1.f / s;
        s_log[t] = e0 * inv;
        s_log[t + 32] = e1 * inv;
    }
    __syncthreads();

    // Phase 4: weighted sum from registers
    float4 acc = make_float4(0.f, 0.f, 0.f, 0.f);
#pragma unroll
    for (int r = 0; r < 8; r++) {
        const float a = s_log[wid * 8 + r];
        acc.x += a * rowA[r].x; acc.y += a * rowA[r].y;
        acc.z += a * rowA[r].z; acc.w += a * rowA[r].w;
        if (hasB) {
            acc.x += a * rowB[r].x; acc.y += a * rowB[r].y;
            acc.z += a * rowB[r].z; acc.w += a * rowB[r].w;
        }
    }
    ((float4*)s_acc[wid])[lane] = acc;
    __syncthreads();

    // Phase 5: cross-warp reduce + store (threads 0..127, one element each)
    if (t < E) {
        float s = s_acc[0][t] + s_acc[1][t] + s_acc[2][t] + s_acc[3][t] +
                  s_acc[4][t] + s_acc[5][t] + s_acc[6][t] + s_acc[7][t];
        float f = scale * (s_self[t] + s);
        g_feats[((size_t)br * B + b) * E + t] = fmaxf(f, 0.f);
    }
}

// ---------------------------------------------------------------------------
// Scores: per-block partial of sum_b tanh(feat_b @ W0 + b0) . w1
// grid (B/SROWS, 3), 256 threads; each warp does 2 rows with 4 accumulators.
// ---------------------------------------------------------------------------
__global__ __launch_bounds__(256) void scores_kernel(
    const float* __restrict__ W0, const float* __restrict__ b0,
    const float* __restrict__ w1, int B)
{
    __shared__ float sW0[E * 64];
    __shared__ float sb0[64];
    __shared__ float sw1[64];
    __shared__ float sfeat[SROWS][E];
    __shared__ float s_part[8];

    const int t = threadIdx.x;
    const int wid = t >> 5, lane = t & 31;
    for (int i = t; i < E * 64; i += 256) sW0[i] = W0[i];
    if (t < 64) { sb0[t] = b0[t]; sw1[t] = w1[t]; }

    const int br = blockIdx.y;
    const int base = blockIdx.x * SROWS;
    const float* fp = g_feats + ((size_t)br * B + base) * E;

    ((float4*)sfeat[wid])[lane]     = ((const float4*)(fp + (size_t)wid * E))[lane];
    ((float4*)sfeat[wid + 8])[lane] = ((const float4*)(fp + (size_t)(wid + 8) * E))[lane];
    __syncthreads();

    float a00 = sb0[lane], a01 = sb0[lane + 32];
    float a10 = a00,       a11 = a01;
#pragma unroll
    for (int e = 0; e < E; e++) {
        const float w0a = sW0[e * 64 + lane];
        const float w0b = sW0[e * 64 + lane + 32];
        const float v0 = sfeat[wid][e];
        const float v1 = sfeat[wid + 8][e];
        a00 += v0 * w0a; a01 += v0 * w0b;
        a10 += v1 * w0a; a11 += v1 * w0b;
    }
    float s = (tanhf(a00) + tanhf(a10)) * sw1[lane] +
              (tanhf(a01) + tanhf(a11)) * sw1[lane + 32];
#pragma unroll
    for (int o = 16; o > 0; o >>= 1) s += __shfl_xor_sync(0xffffffffu, s, o);
    if (lane == 0) s_part[wid] = s;
    __syncthreads();
    if (t == 0) {
        g_part[br * MAX_PARTS + blockIdx.x] =
            s_part[0] + s_part[1] + s_part[2] + s_part[3] +
            s_part[4] + s_part[5] + s_part[6] + s_part[7];
    }
}

__global__ void reduce_scores_kernel(int nparts) {
    const int br = blockIdx.x;
    const int t = threadIdx.x;
    float v = 0.f;
    for (int i = t; i < nparts; i += 256) v += g_part[br * MAX_PARTS + i];
#pragma unroll
    for (int o = 16; o > 0; o >>= 1) v += __shfl_xor_sync(0xffffffffu, v, o);
    __shared__ float red[8];
    if ((t & 31) == 0) red[t >> 5] = v;
    __syncthreads();
    if (t == 0) {
        float s = 0.f;
#pragma unroll
        for (int i = 0; i < 8; i++) s += red[i];
        g_scores[br] = s;
    }
}

__global__ void mix_kernel(float* __restrict__ out, int B) {
    const int i = blockIdx.x * blockDim.x + threadIdx.x;
    const int total = B * E;
    if (i >= total) return;
    const float inv = 1.f / (float)B;
    float s0 = g_scores[0] * inv, s1 = g_scores[1] * inv, s2 = g_scores[2] * inv;
    float m = fmaxf(s0, fmaxf(s1, s2));
    float e0 = expf(s0 - m), e1 = expf(s1 - m), e2 = expf(s2 - m);
    float d = 1.f / (e0 + e1 + e2);
    float v = (e0 * g_feats[i] +
               e1 * g_feats[(size_t)B * E + i] +
               e2 * g_feats[(size_t)2 * B * E + i]) * d;
    out[i] = fmaxf(v, 0.f);
}

extern "C" void kernel_launch(void* const* d_in, const int* in_sizes, int n_in,
                              void* d_out, int out_size) {
    const float* user_embs = (const float*)d_in[0];
    const float* item_embs = (const float*)d_in[1];
    const float* w_uu  = (const float*)d_in[2];
    const float* w_uiu = (const float*)d_in[3];
    const float* w_uui = (const float*)d_in[4];
    const float* W0 = (const float*)d_in[5];
    const float* b0 = (const float*)d_in[6];
    const float* w1 = (const float*)d_in[7];
    const int* uid = (const int*)d_in[8];
    const int* nbr = (const int*)d_in[9];
    const int* uiu = (const int*)d_in[10];
    const int* uui = (const int*)d_in[11];
    float* out = (float*)d_out;

    const int B = in_sizes[8];

    dim3 g1(B, 3);
    branch_kernel<<<g1, 256>>>(user_embs, item_embs, w_uu, w_uiu, w_uui,
                               uid, nbr, uiu, uui, B);

    const int nparts = B / SROWS;
    dim3 g2(nparts, 3);
    scores_kernel<<<g2, 256>>>(W0, b0, w1, B);
    reduce_scores_kernel<<<3, 256>>>(nparts);

    const int total = B * E;
    mix_kernel<<<(total + 255) / 256, 256>>>(out, B);
}

// round 3
// speedup vs baseline: 2.5336x; 1.3260x over previous
#include <cuda_runtime.h>
#include <cstdint>

#define E 128
#define L 64
#define NEG_INF -100000000.0f
#define MAX_B 8192
#define SROWS 16
#define MAX_PARTS (MAX_B / SROWS)

__device__ __align__(16) float g_feats[3ull * MAX_B * E];
__device__ float g_part[3 * MAX_PARTS];
__device__ float g_scores[3];

__device__ __forceinline__ void cp_async16(void* smem_dst, const void* gsrc) {
    uint32_t s = (uint32_t)__cvta_generic_to_shared(smem_dst);
    asm volatile("cp.async.cg.shared.global [%0], [%1], 16;\n" :: "r"(s), "l"(gsrc));
}
__device__ __forceinline__ void cp_commit() { asm volatile("cp.async.commit_group;\n"); }
__device__ __forceinline__ void cp_wait0()  { asm volatile("cp.async.wait_group 0;\n"); }

// ---------------------------------------------------------------------------
// Fused branch kernel: grid (B, 3), 256 threads.
// Table-A rows register-resident; table-B rows streamed via cp.async -> smem.
// ---------------------------------------------------------------------------
__global__ __launch_bounds__(256) void branch_kernel(
    const float* __restrict__ user_embs, const float* __restrict__ item_embs,
    const float* __restrict__ w_uu, const float* __restrict__ w_uiu,
    const float* __restrict__ w_uui,
    const int* __restrict__ uid, const int* __restrict__ nbr,
    const int* __restrict__ uiu, const int* __restrict__ uui, int B)
{
    __shared__ int   s_idx[2 * L];
    __shared__ float s_self[E];
    __shared__ float s_whi[E];
    __shared__ float s_log[L];
    __shared__ float s_red[8];
    __shared__ float s_acc[8][E];
    __shared__ __align__(16) float tileB[L * E];   // 32 KB

    const int t    = threadIdx.x;
    const int wid  = t >> 5;
    const int lane = t & 31;
    const int b    = blockIdx.x;
    const int br   = blockIdx.y;

    const float* tabA; const float* tabB; const float* w;
    const int* idx; int stride; float scale; bool hasB;
    if (br == 0)      { tabA = user_embs; tabB = user_embs; w = w_uu;  idx = nbr; stride = L;     scale = 0.5f;    hasB = false; }
    else if (br == 1) { tabA = item_embs; tabB = user_embs; w = w_uiu; idx = uiu; stride = 2 * L; scale = 1.f/3.f; hasB = true; }
    else              { tabA = user_embs; tabB = item_embs; w = w_uui; idx = uui; stride = 2 * L; scale = 1.f/3.f; hasB = true; }

    // Phase 0: warps 0-3 load indices; warps 4-7 load self/w and do self-dots.
    if (t < stride) s_idx[t] = idx[(size_t)b * stride + t];
    if (t >= 128) {
        const int e = t - 128;
        const int u = uid[b];
        const float se  = user_embs[(size_t)u * E + e];
        const float wlo = w[e];
        const float whi = w[E + e];
        s_self[e] = se;
        s_whi[e]  = whi;
        float p0 = se * wlo, p1 = se * whi;
#pragma unroll
        for (int o = 16; o > 0; o >>= 1) {
            p0 += __shfl_xor_sync(0xffffffffu, p0, o);
            p1 += __shfl_xor_sync(0xffffffffu, p1, o);
        }
        if (lane == 0) { s_red[wid - 4] = p0; s_red[4 + (wid - 4)] = p1; }
    }
    __syncthreads();

    // Phase 1: gathers. B rows via cp.async into smem (no register cost),
    // A rows into registers. Each warp owns rows wid*8 .. wid*8+7.
    if (hasB) {
#pragma unroll
        for (int r = 0; r < 8; r++) {
            const int l = wid * 8 + r;
            cp_async16(&tileB[l * E + lane * 4],
                       tabB + (size_t)s_idx[L + l] * E + lane * 4);
        }
        cp_commit();
    }
    float4 rowA[8];
#pragma unroll
    for (int r = 0; r < 8; r++) {
        const int l = wid * 8 + r;
        rowA[r] = ((const float4*)(tabA + (size_t)s_idx[l] * E))[lane];
    }

    const float c_lo = s_red[0] + s_red[1] + s_red[2] + s_red[3];
    const float c_hi = s_red[4] + s_red[5] + s_red[6] + s_red[7];
    const float4 wh = ((const float4*)s_whi)[lane];

    if (hasB) cp_wait0();   // each lane re-reads only the 16B it copied

    // Phase 2: per-row logits
#pragma unroll
    for (int r = 0; r < 8; r++) {
        const int l = wid * 8 + r;
        float d = rowA[r].x * wh.x + rowA[r].y * wh.y +
                  rowA[r].z * wh.z + rowA[r].w * wh.w;
        if (hasB) {
            const float4 vb = ((const float4*)(tileB + l * E))[lane];
            d += vb.x * wh.x + vb.y * wh.y + vb.z * wh.z + vb.w * wh.w;
        }
#pragma unroll
        for (int o = 16; o > 0; o >>= 1) d += __shfl_xor_sync(0xffffffffu, d, o);
        if (lane == 0) {
            float x = c_lo + scale * (c_hi + d);
            x = (x > 0.f) ? x : 0.01f * x;
            if (s_idx[l] == 0) x += NEG_INF;
            s_log[l] = x;
        }
    }
    __syncthreads();

    // Phase 3: softmax over L=64 (warp 0)
    if (t < 32) {
        float v0 = s_log[t], v1 = s_log[t + 32];
        float m = fmaxf(v0, v1);
#pragma unroll
        for (int o = 16; o > 0; o >>= 1) m = fmaxf(m, __shfl_xor_sync(0xffffffffu, m, o));
        float e0 = expf(v0 - m), e1 = expf(v1 - m);
        float s = e0 + e1;
#pragma unroll
        for (int o = 16; o > 0; o >>= 1) s += __shfl_xor_sync(0xffffffffu, s, o);
        float inv = 1.f / s;
        s_log[t] = e0 * inv;
        s_log[t + 32] = e1 * inv;
    }
    __syncthreads();

    // Phase 4: weighted sum (A from regs, B from smem, own rows only)
    float4 acc = make_float4(0.f, 0.f, 0.f, 0.f);
#pragma unroll
    for (int r = 0; r < 8; r++) {
        const int l = wid * 8 + r;
        const float a = s_log[l];
        acc.x += a * rowA[r].x; acc.y += a * rowA[r].y;
        acc.z += a * rowA[r].z; acc.w += a * rowA[r].w;
        if (hasB) {
            const float4 vb = ((const float4*)(tileB + l * E))[lane];
            acc.x += a * vb.x; acc.y += a * vb.y;
            acc.z += a * vb.z; acc.w += a * vb.w;
        }
    }
    ((float4*)s_acc[wid])[lane] = acc;
    __syncthreads();

    // Phase 5: cross-warp reduce + store
    if (t < E) {
        float s = s_acc[0][t] + s_acc[1][t] + s_acc[2][t] + s_acc[3][t] +
                  s_acc[4][t] + s_acc[5][t] + s_acc[6][t] + s_acc[7][t];
        float f = scale * (s_self[t] + s);
        g_feats[((size_t)br * B + b) * E + t] = fmaxf(f, 0.f);
    }
}

// ---------------------------------------------------------------------------
// Scores: per-block partial of sum_b tanh(feat_b @ W0 + b0) . w1
// ---------------------------------------------------------------------------
__global__ __launch_bounds__(256) void scores_kernel(
    const float* __restrict__ W0, const float* __restrict__ b0,
    const float* __restrict__ w1, int B)
{
    __shared__ float sW0[E * 64];
    __shared__ float sb0[64];
    __shared__ float sw1[64];
    __shared__ float sfeat[SROWS][E];
    __shared__ float s_part[8];

    const int t = threadIdx.x;
    const int wid = t >> 5, lane = t & 31;
    for (int i = t; i < E * 64; i += 256) sW0[i] = W0[i];
    if (t < 64) { sb0[t] = b0[t]; sw1[t] = w1[t]; }

    const int br = blockIdx.y;
    const int base = blockIdx.x * SROWS;
    const float* fp = g_feats + ((size_t)br * B + base) * E;

    ((float4*)sfeat[wid])[lane]     = ((const float4*)(fp + (size_t)wid * E))[lane];
    ((float4*)sfeat[wid + 8])[lane] = ((const float4*)(fp + (size_t)(wid + 8) * E))[lane];
    __syncthreads();

    float a00 = sb0[lane], a01 = sb0[lane + 32];
    float a10 = a00,       a11 = a01;
#pragma unroll
    for (int e = 0; e < E; e++) {
        const float w0a = sW0[e * 64 + lane];
        const float w0b = sW0[e * 64 + lane + 32];
        const float v0 = sfeat[wid][e];
        const float v1 = sfeat[wid + 8][e];
        a00 += v0 * w0a; a01 += v0 * w0b;
        a10 += v1 * w0a; a11 += v1 * w0b;
    }
    float s = (tanhf(a00) + tanhf(a10)) * sw1[lane] +
              (tanhf(a01) + tanhf(a11)) * sw1[lane + 32];
#pragma unroll
    for (int o = 16; o > 0; o >>= 1) s += __shfl_xor_sync(0xffffffffu, s, o);
    if (lane == 0) s_part[wid] = s;
    __syncthreads();
    if (t == 0) {
        g_part[br * MAX_PARTS + blockIdx.x] =
            s_part[0] + s_part[1] + s_part[2] + s_part[3] +
            s_part[4] + s_part[5] + s_part[6] + s_part[7];
    }
}

__global__ void reduce_scores_kernel(int nparts) {
    const int br = blockIdx.x;
    const int t = threadIdx.x;
    float v = 0.f;
    for (int i = t; i < nparts; i += 256) v += g_part[br * MAX_PARTS + i];
#pragma unroll
    for (int o = 16; o > 0; o >>= 1) v += __shfl_xor_sync(0xffffffffu, v, o);
    __shared__ float red[8];
    if ((t & 31) == 0) red[t >> 5] = v;
    __syncthreads();
    if (t == 0) {
        float s = 0.f;
#pragma unroll
        for (int i = 0; i < 8; i++) s += red[i];
        g_scores[br] = s;
    }
}

__global__ void mix_kernel(float4* __restrict__ out, int B) {
    const int i = blockIdx.x * blockDim.x + threadIdx.x;
    const int total = B * E / 4;
    if (i >= total) return;
    const float inv = 1.f / (float)B;
    float s0 = g_scores[0] * inv, s1 = g_scores[1] * inv, s2 = g_scores[2] * inv;
    float m = fmaxf(s0, fmaxf(s1, s2));
    float e0 = expf(s0 - m), e1 = expf(s1 - m), e2 = expf(s2 - m);
    float d = 1.f / (e0 + e1 + e2);
    const float4* f0 = (const float4*)g_feats;
    const float4* f1 = (const float4*)(g_feats + (size_t)B * E);
    const float4* f2 = (const float4*)(g_feats + (size_t)2 * B * E);
    float4 a = f0[i], b4 = f1[i], c = f2[i];
    float4 r;
    r.x = fmaxf((e0 * a.x + e1 * b4.x + e2 * c.x) * d, 0.f);
    r.y = fmaxf((e0 * a.y + e1 * b4.y + e2 * c.y) * d, 0.f);
    r.z = fmaxf((e0 * a.z + e1 * b4.z + e2 * c.z) * d, 0.f);
    r.w = fmaxf((e0 * a.w + e1 * b4.w + e2 * c.w) * d, 0.f);
    out[i] = r;
}

extern "C" void kernel_launch(void* const* d_in, const int* in_sizes, int n_in,
                              void* d_out, int out_size) {
    const float* user_embs = (const float*)d_in[0];
    const float* item_embs = (const float*)d_in[1];
    const float* w_uu  = (const float*)d_in[2];
    const float* w_uiu = (const float*)d_in[3];
    const float* w_uui = (const float*)d_in[4];
    const float* W0 = (const float*)d_in[5];
    const float* b0 = (const float*)d_in[6];
    const float* w1 = (const float*)d_in[7];
    const int* uid = (const int*)d_in[8];
    const int* nbr = (const int*)d_in[9];
    const int* uiu = (const int*)d_in[10];
    const int* uui = (const int*)d_in[11];
    float* out = (float*)d_out;

    const int B = in_sizes[8];

    dim3 g1(B, 3);
    branch_kernel<<<g1, 256>>>(user_embs, item_embs, w_uu, w_uiu, w_uui,
                               uid, nbr, uiu, uui, B);

    const int nparts = B / SROWS;
    dim3 g2(nparts, 3);
    scores_kernel<<<g2, 256>>>(W0, b0, w1, B);
    reduce_scores_kernel<<<3, 256>>>(nparts);

    const int total4 = B * E / 4;
    mix_kernel<<<(total4 + 255) / 256, 256>>>((float4*)out, B);
}